// round 8
// baseline (speedup 1.0000x reference)
#include <cuda_runtime.h>
#include <math.h>

// Problem constants
#define BB 128
#define TT 256
#define CC 384
#define HH 6
#define DD 64
#define NQKV 1152   // 3*CC
#define KDIM 384
#define MTOT (BB*TT)   // 32768

// Scratch in device globals (no cudaMalloc allowed).
// __align__(16): these are accessed via float4/u64 wide loads; plain float[]
// only guarantees 4B alignment and a misaligned LDG.128 traps (err715).
__device__ __align__(16) float g_Q[BB*HH*TT*DD];     // [b,h,t,d] rope-applied, pre-scaled
__device__ __align__(16) float g_K[BB*HH*TT*DD];     // [b,h,t,d] rope-applied
__device__ __align__(16) float g_V[BB*HH*TT*DD];     // [b,h,t,d]
__device__ __align__(16) float g_AttnOut[BB*TT*CC];  // [b,t,c]

typedef unsigned long long u64;

// ---------------- f32x2 packed helpers (sm_103a FFMA2) ----------------------
__device__ __forceinline__ u64 packf2(float lo, float hi) {
    u64 r;
    asm("mov.b64 %0, {%1, %2};" : "=l"(r)
        : "r"(__float_as_uint(lo)), "r"(__float_as_uint(hi)));
    return r;
}
// d += a*b   (elementwise on the two packed lanes)
__device__ __forceinline__ void fma2(u64& d, u64 a, u64 b) {
    asm("fma.rn.f32x2 %0, %1, %2, %0;" : "+l"(d) : "l"(a), "l"(b));
}
// d = a*b + c
__device__ __forceinline__ void fma2o(u64& d, u64 a, u64 b, u64 c) {
    asm("fma.rn.f32x2 %0, %1, %2, %3;" : "=l"(d) : "l"(a), "l"(b), "l"(c));
}
__device__ __forceinline__ float sumf2(u64 v) {
    unsigned int lo, hi;
    asm("mov.b64 {%0, %1}, %2;" : "=r"(lo), "=r"(hi) : "l"(v));
    return __uint_as_float(lo) + __uint_as_float(hi);
}
__device__ __forceinline__ void unpackf2(u64 v, float& lo, float& hi) {
    unsigned int l_, h_;
    asm("mov.b64 {%0, %1}, %2;" : "=r"(l_), "=r"(h_) : "l"(v));
    lo = __uint_as_float(l_); hi = __uint_as_float(h_);
}

// ---------------------------------------------------------------------------
// f32x2 GEMM core layout (audited):
//   CTA tile: 128 (M) x 64 (N), Ktile = 16 (8 k-pairs), 256 threads.
//   Thread tile: 4 rows x 8 cols (4 column-PAIRS, strided by 8 so LDS.64 B
//   reads are conflict-free; pair columns adjacent so RoPE stays local).
//   Accumulators vectorized over k (lo=even k, hi=odd k), reduced at the end.
//   Smem rows padded to 9 u64: odd 8B stride -> conflict-free LDS.64.
// ---------------------------------------------------------------------------

// Kernel 1: qkv = x @ W_qkv, fused RoPE + head scatter. Q pre-scaled by 1/8.
__global__ void __launch_bounds__(256) qkv_rope_kernel(
    const float* __restrict__ x, const float* __restrict__ Wqkv)
{
    __shared__ u64 As[2][128][9];  // [buf][m][k-pair]
    __shared__ u64 Bs[2][64][9];   // [buf][n][k-pair]

    const int tid = threadIdx.x;
    const int txp = tid & 7;
    const int tyy = tid >> 3;
    const int m0 = blockIdx.y * 128;
    const int n0 = blockIdx.x * 64;

    const int ar = tid >> 2;
    const int aq = tid & 3;
    const int bk = tid >> 4;
    const int bc = (tid & 15) * 4;

    u64 acc2[4][8];
#pragma unroll
    for (int i = 0; i < 4; i++)
#pragma unroll
        for (int j = 0; j < 8; j++) acc2[i][j] = 0ULL;

    const int NT = KDIM / 16;   // 24

    {
        float4 a0 = *(const float4*)&x[(size_t)(m0 + ar) * KDIM + aq * 4];
        float4 a1 = *(const float4*)&x[(size_t)(m0 + ar + 64) * KDIM + aq * 4];
        As[0][ar][aq * 2 + 0]      = packf2(a0.x, a0.y);
        As[0][ar][aq * 2 + 1]      = packf2(a0.z, a0.w);
        As[0][ar + 64][aq * 2 + 0] = packf2(a1.x, a1.y);
        As[0][ar + 64][aq * 2 + 1] = packf2(a1.z, a1.w);
        float4 bv = *(const float4*)&Wqkv[(size_t)bk * NQKV + n0 + bc];
        float* bf = (float*)&Bs[0][0][0];   // row stride 18 floats
        bf[(bc + 0) * 18 + bk] = bv.x;
        bf[(bc + 1) * 18 + bk] = bv.y;
        bf[(bc + 2) * 18 + bk] = bv.z;
        bf[(bc + 3) * 18 + bk] = bv.w;
    }
    __syncthreads();

    for (int kt = 0; kt < NT; kt++) {
        const int cur = kt & 1;
        float4 a0, a1, bv;
        const bool more = (kt + 1 < NT);
        if (more) {
            const int k0 = (kt + 1) * 16;
            a0 = *(const float4*)&x[(size_t)(m0 + ar) * KDIM + k0 + aq * 4];
            a1 = *(const float4*)&x[(size_t)(m0 + ar + 64) * KDIM + k0 + aq * 4];
            bv = *(const float4*)&Wqkv[(size_t)(k0 + bk) * NQKV + n0 + bc];
        }

#pragma unroll
        for (int kp = 0; kp < 8; kp++) {
            u64 a2[4], b2[8];
#pragma unroll
            for (int i = 0; i < 4; i++) a2[i] = As[cur][tyy * 4 + i][kp];
#pragma unroll
            for (int jp = 0; jp < 4; jp++) {
                const int c = 2 * (txp + 8 * jp);
                b2[jp * 2 + 0] = Bs[cur][c + 0][kp];
                b2[jp * 2 + 1] = Bs[cur][c + 1][kp];
            }
#pragma unroll
            for (int i = 0; i < 4; i++)
#pragma unroll
                for (int j = 0; j < 8; j++) fma2(acc2[i][j], a2[i], b2[j]);
        }

        if (more) {
            const int nxt = cur ^ 1;
            As[nxt][ar][aq * 2 + 0]      = packf2(a0.x, a0.y);
            As[nxt][ar][aq * 2 + 1]      = packf2(a0.z, a0.w);
            As[nxt][ar + 64][aq * 2 + 0] = packf2(a1.x, a1.y);
            As[nxt][ar + 64][aq * 2 + 1] = packf2(a1.z, a1.w);
            float* bf = (float*)&Bs[nxt][0][0];
            bf[(bc + 0) * 18 + bk] = bv.x;
            bf[(bc + 1) * 18 + bk] = bv.y;
            bf[(bc + 2) * 18 + bk] = bv.z;
            bf[(bc + 3) * 18 + bk] = bv.w;
            __syncthreads();
        }
    }

    // Epilogue: reduce pairs, RoPE on Q/K column pairs, scatter to [b,h,t,d].
    // Q additionally pre-scaled by 1/sqrt(64) = 0.125 for the attention stage.
    const float NEG_LNB_64 = -0.14391156872729044f;   // -ln(10000)/64
#pragma unroll
    for (int jp = 0; jp < 4; jp++) {
        const int p = txp + 8 * jp;
        const int ncol = n0 + 2 * p;           // even
        const int sec = ncol / CC;             // 0=q 1=k 2=v
        const int within = ncol - sec * CC;
        const int h = within >> 6;
        const int d0 = within & 63;            // even
        const float invf = __expf(NEG_LNB_64 * (float)d0);
#pragma unroll
        for (int i = 0; i < 4; i++) {
            const int m = m0 + tyy * 4 + i;
            const int b = m >> 8;
            const int t = m & 255;
            float u = sumf2(acc2[i][jp * 2 + 0]);
            float v = sumf2(acc2[i][jp * 2 + 1]);
            float* dst;
            if (sec == 2) {
                dst = g_V;
            } else {
                const float f = (float)t * invf;
                const float cs = cosf(f), sn = sinf(f);
                float ru = u * cs - v * sn;
                float rv = v * cs + u * sn;
                if (sec == 0) { ru *= 0.125f; rv *= 0.125f; dst = g_Q; }
                else          { dst = g_K; }
                u = ru; v = rv;
            }
            *(float2*)&dst[(((size_t)b * HH + h) * TT + t) * DD + d0] =
                make_float2(u, v);
        }
    }
}

// ---------------------------------------------------------------------------
// Kernel 2: causal attention per (b,h). One block per (b,h), 256 threads,
// one thread per query row. K/V streamed through smem in 64-row chunks.
// f32x2-packed dot and PV accumulate; online softmax, rescale only on
// running-max update. Q comes in pre-scaled by 1/sqrt(D).
// ---------------------------------------------------------------------------
__global__ void __launch_bounds__(256) attn_kernel()
{
    __shared__ u64 Ks2[64 * 32];   // 64 rows x 32 d-pairs
    __shared__ u64 Vs2[64 * 32];

    const int bh = blockIdx.x;
    const int tid = threadIdx.x;
    const int t = tid;                 // query row
    const size_t base = (size_t)bh * TT * DD;

    // q row (pre-scaled) as 32 packed pairs
    u64 q2[32];
    {
        const u64* qp = (const u64*)(g_Q + base + (size_t)t * DD);
#pragma unroll
        for (int i = 0; i < 32; i++) q2[i] = qp[i];
    }

    u64 acc2[32];
#pragma unroll
    for (int i = 0; i < 32; i++) acc2[i] = 0ULL;
    float mrun = -1e30f;
    float l = 0.f;

    for (int c = 0; c < TT / 64; c++) {
        const float4* Kg4 = (const float4*)(g_K + base + (size_t)c * 64 * DD);
        const float4* Vg4 = (const float4*)(g_V + base + (size_t)c * 64 * DD);
        float4* Ks4 = (float4*)Ks2;
        float4* Vs4 = (float4*)Vs2;
#pragma unroll 4
        for (int idx = tid; idx < 64 * 16; idx += 256) {
            Ks4[idx] = Kg4[idx];
            Vs4[idx] = Vg4[idx];
        }
        __syncthreads();

        const int kkend = min(t + 1 - c * 64, 64);
        for (int kk = 0; kk < kkend; kk++) {
            const u64* krow = &Ks2[kk * 32];
            // 4 independent accumulator chains, depth 8 each
            u64 s2a = 0ULL, s2b = 0ULL, s2c = 0ULL, s2d = 0ULL;
#pragma unroll
            for (int d = 0; d < 8; d++) {
                fma2(s2a, q2[4 * d + 0], krow[4 * d + 0]);
                fma2(s2b, q2[4 * d + 1], krow[4 * d + 1]);
                fma2(s2c, q2[4 * d + 2], krow[4 * d + 2]);
                fma2(s2d, q2[4 * d + 3], krow[4 * d + 3]);
            }
            const float s = (sumf2(s2a) + sumf2(s2b)) + (sumf2(s2c) + sumf2(s2d));
            const u64* vrow = &Vs2[kk * 32];
            if (s <= mrun) {
                const float p = __expf(s - mrun);
                l += p;
                const u64 pp = packf2(p, p);
#pragma unroll
                for (int d = 0; d < 32; d++) fma2(acc2[d], pp, vrow[d]);
            } else {
                const float r = __expf(mrun - s);
                l = fmaf(l, r, 1.f);
                const u64 rr = packf2(r, r);
#pragma unroll
                for (int d = 0; d < 32; d++) fma2o(acc2[d], acc2[d], rr, vrow[d]);
                mrun = s;
            }
        }
        __syncthreads();
    }

    const float inv = 1.f / l;
    const int b = bh / HH;
    const int h = bh - b * HH;
    float2* __restrict__ op =
        (float2*)&g_AttnOut[((size_t)b * TT + t) * CC + h * DD];
#pragma unroll
    for (int d = 0; d < 32; d++) {
        float lo, hi;
        unpackf2(acc2[d], lo, hi);
        op[d] = make_float2(lo * inv, hi * inv);
    }
}

// ---------------------------------------------------------------------------
// Kernel 3: out = AttnOut @ W_proj (32768 x 384 x 384). Same f32x2 GEMM core.
// ---------------------------------------------------------------------------
__global__ void __launch_bounds__(256) proj_kernel(
    const float* __restrict__ Wproj, float* __restrict__ out)
{
    __shared__ u64 As[2][128][9];
    __shared__ u64 Bs[2][64][9];

    const int tid = threadIdx.x;
    const int txp = tid & 7;
    const int tyy = tid >> 3;
    const int m0 = blockIdx.y * 128;
    const int n0 = blockIdx.x * 64;

    const int ar = tid >> 2;
    const int aq = tid & 3;
    const int bk = tid >> 4;
    const int bc = (tid & 15) * 4;

    u64 acc2[4][8];
#pragma unroll
    for (int i = 0; i < 4; i++)
#pragma unroll
        for (int j = 0; j < 8; j++) acc2[i][j] = 0ULL;

    const int NT = CC / 16;   // 24

    {
        float4 a0 = *(const float4*)&g_AttnOut[(size_t)(m0 + ar) * CC + aq * 4];
        float4 a1 = *(const float4*)&g_AttnOut[(size_t)(m0 + ar + 64) * CC + aq * 4];
        As[0][ar][aq * 2 + 0]      = packf2(a0.x, a0.y);
        As[0][ar][aq * 2 + 1]      = packf2(a0.z, a0.w);
        As[0][ar + 64][aq * 2 + 0] = packf2(a1.x, a1.y);
        As[0][ar + 64][aq * 2 + 1] = packf2(a1.z, a1.w);
        float4 bv = *(const float4*)&Wproj[(size_t)bk * CC + n0 + bc];
        float* bf = (float*)&Bs[0][0][0];
        bf[(bc + 0) * 18 + bk] = bv.x;
        bf[(bc + 1) * 18 + bk] = bv.y;
        bf[(bc + 2) * 18 + bk] = bv.z;
        bf[(bc + 3) * 18 + bk] = bv.w;
    }
    __syncthreads();

    for (int kt = 0; kt < NT; kt++) {
        const int cur = kt & 1;
        float4 a0, a1, bv;
        const bool more = (kt + 1 < NT);
        if (more) {
            const int k0 = (kt + 1) * 16;
            a0 = *(const float4*)&g_AttnOut[(size_t)(m0 + ar) * CC + k0 + aq * 4];
            a1 = *(const float4*)&g_AttnOut[(size_t)(m0 + ar + 64) * CC + k0 + aq * 4];
            bv = *(const float4*)&Wproj[(size_t)(k0 + bk) * CC + n0 + bc];
        }

#pragma unroll
        for (int kp = 0; kp < 8; kp++) {
            u64 a2[4], b2[8];
#pragma unroll
            for (int i = 0; i < 4; i++) a2[i] = As[cur][tyy * 4 + i][kp];
#pragma unroll
            for (int jp = 0; jp < 4; jp++) {
                const int c = 2 * (txp + 8 * jp);
                b2[jp * 2 + 0] = Bs[cur][c + 0][kp];
                b2[jp * 2 + 1] = Bs[cur][c + 1][kp];
            }
#pragma unroll
            for (int i = 0; i < 4; i++)
#pragma unroll
                for (int j = 0; j < 8; j++) fma2(acc2[i][j], a2[i], b2[j]);
        }

        if (more) {
            const int nxt = cur ^ 1;
            As[nxt][ar][aq * 2 + 0]      = packf2(a0.x, a0.y);
            As[nxt][ar][aq * 2 + 1]      = packf2(a0.z, a0.w);
            As[nxt][ar + 64][aq * 2 + 0] = packf2(a1.x, a1.y);
            As[nxt][ar + 64][aq * 2 + 1] = packf2(a1.z, a1.w);
            float* bf = (float*)&Bs[nxt][0][0];
            bf[(bc + 0) * 18 + bk] = bv.x;
            bf[(bc + 1) * 18 + bk] = bv.y;
            bf[(bc + 2) * 18 + bk] = bv.z;
            bf[(bc + 3) * 18 + bk] = bv.w;
            __syncthreads();
        }
    }

#pragma unroll
    for (int jp = 0; jp < 4; jp++) {
        const int ncol = n0 + 2 * (txp + 8 * jp);
#pragma unroll
        for (int i = 0; i < 4; i++) {
            const int m = m0 + tyy * 4 + i;
            *(float2*)&out[(size_t)m * CC + ncol] =
                make_float2(sumf2(acc2[i][jp * 2 + 0]),
                            sumf2(acc2[i][jp * 2 + 1]));
        }
    }
}

// ---------------------------------------------------------------------------
extern "C" void kernel_launch(void* const* d_in, const int* in_sizes, int n_in,
                              void* d_out, int out_size)
{
    const float* x     = (const float*)d_in[0];
    const float* Wqkv  = (const float*)d_in[1];
    const float* Wproj = (const float*)d_in[2];
    float* out = (float*)d_out;

    // 1. QKV GEMM + RoPE + head scatter  (tiles: 128 M x 64 N)
    {
        dim3 grid(NQKV / 64, MTOT / 128);  // (18, 256)
        qkv_rope_kernel<<<grid, 256>>>(x, Wqkv);
    }
    // 2. Causal attention
    attn_kernel<<<BB * HH, 256>>>();
    // 3. Output projection
    {
        dim3 grid(CC / 64, MTOT / 128);    // (6, 256)
        proj_kernel<<<grid, 256>>>(Wproj, out);
    }
}